// round 7
// baseline (speedup 1.0000x reference)
#include <cuda_runtime.h>
#include <cstdint>

#define N_NODES 50000
#define N_EDGES 800000

// ---------------- scratch (static device allocation) ---------------------------
__device__ float g_summed[N_NODES * 64];   // scatter-sum of hidden h (pre-W1b)
__device__ float g_counts[N_NODES];
__device__ float g_agg[N_NODES * 64];      // (summed/cnt)@W1b + b1b

// ---------------- helpers -------------------------------------------------------
__device__ __forceinline__ uint32_t smem_u32(const void* p) {
    uint32_t a;
    asm("{ .reg .u64 t; cvta.to.shared.u64 t, %1; cvt.u32.u64 %0, t; }" : "=r"(a) : "l"(p));
    return a;
}
__device__ __forceinline__ uint32_t to_tf32(float f) {
    uint32_t r; asm("cvt.rna.tf32.f32 %0, %1;" : "=r"(r) : "f"(f)); return r;
}
__device__ __forceinline__ void red4(float* a, float4 v) {
    asm volatile("red.global.add.v4.f32 [%0], {%1,%2,%3,%4};"
                 :: "l"(a), "f"(v.x), "f"(v.y), "f"(v.z), "f"(v.w) : "memory");
}
__device__ __forceinline__ void barp(int id) {
    asm volatile("bar.sync %0, 64;" :: "r"(id) : "memory");
}
__device__ __forceinline__ void cp16(uint32_t dst, const void* src) {
    asm volatile("cp.async.cg.shared.global [%0], [%1], 16;" :: "r"(dst), "l"(src) : "memory");
}
__device__ __forceinline__ void cp_commit() {
    asm volatile("cp.async.commit_group;" ::: "memory");
}
template <int N> __device__ __forceinline__ void cp_wait() {
    asm volatile("cp.async.wait_group %0;" :: "n"(N) : "memory");
}
// m16n8k8 tf32 MMA. g = lane>>2, c = lane&3:
//   A: a0=A[g][c] a1=A[g+8][c] a2=A[g][c+4] a3=A[g+8][c+4]
//   B: b0=B[c][n] b1=B[c+4][n]  (n = lane>>2)
//   D: d0=D[g][2c] d1=D[g][2c+1] d2=D[g+8][2c] d3=D[g+8][2c+1]
__device__ __forceinline__ void mma8(float d[4], const uint32_t a[4],
                                     uint32_t b0, uint32_t b1) {
    asm("mma.sync.aligned.m16n8k8.row.col.f32.tf32.tf32.f32 "
        "{%0,%1,%2,%3}, {%4,%5,%6,%7}, {%8,%9}, {%0,%1,%2,%3};"
        : "+f"(d[0]), "+f"(d[1]), "+f"(d[2]), "+f"(d[3])
        : "r"(a[0]), "r"(a[1]), "r"(a[2]), "r"(a[3]), "r"(b0), "r"(b1));
}

// ---------------- weight staging variants -------------------------------------------
// (a) nb-pair packed, single tf32 (edge): sW[(kc*4+nbp)*32+lane] =
//     {b0(nb=2nbp), b1(nb=2nbp), b0(nb=2nbp+1), b1(nb=2nbp+1)}
template <int KC, int NTHR>
__device__ __forceinline__ void stage_w_p4(uint4* sW, const float* __restrict__ W, int tid) {
    for (int i = tid; i < KC * 128; i += NTHR) {
        const int kc = i >> 7, nbp = (i >> 5) & 3, t = i & 31;
        const int k0 = kc * 8 + (t & 3);
        const int n0 = (2 * nbp) * 8 + (t >> 2), n1 = n0 + 8;
        uint4 fr;
        fr.x = to_tf32(W[k0 * 64 + n0]);
        fr.y = to_tf32(W[(k0 + 4) * 64 + n0]);
        fr.z = to_tf32(W[k0 * 64 + n1]);
        fr.w = to_tf32(W[(k0 + 4) * 64 + n1]);
        sW[i] = fr;
    }
}
// (b) hi/lo packed, exact weights (agg/node): sW[(kc*8+nb)*32+lane] = {b0h,b1h,b0l,b1l}
template <int KC, int NTHR>
__device__ __forceinline__ void stage_w_hl(uint4* sW, const float* __restrict__ W, int tid) {
    for (int i = tid; i < KC * 256; i += NTHR) {
        const int kc = i >> 8, nb = (i >> 5) & 7, t = i & 31;
        const int k0 = kc * 8 + (t & 3), n = nb * 8 + (t >> 2);
        const float w0 = W[k0 * 64 + n], w1 = W[(k0 + 4) * 64 + n];
        uint4 fr;
        fr.x = to_tf32(w0); fr.y = to_tf32(w1);
        fr.z = to_tf32(w0 - __uint_as_float(fr.x));
        fr.w = to_tf32(w1 - __uint_as_float(fr.y));
        sW[i] = fr;
    }
}

// ---------------- GEMM cores ----------------------------------------------------------
// hi/lo exact-weight GEMM: warp = 16 rows x 32 cols (agg/node)
template <int KC>
__device__ __forceinline__ void gemm_hl(const float* __restrict__ sIn, int lds,
                                        const uint4* __restrict__ sWf,
                                        int tg, int tc, int lane, int cg, float acc[4][4]) {
#pragma unroll
    for (int nb = 0; nb < 4; ++nb)
#pragma unroll
        for (int j = 0; j < 4; ++j) acc[nb][j] = 0.0f;
    const float* p0 = sIn + tg * lds;
#pragma unroll 4
    for (int kc = 0; kc < KC; ++kc) {
        const float* q = p0 + kc * 8 + tc;
        uint32_t a[4];
        a[0] = __float_as_uint(q[0]);
        a[1] = __float_as_uint(q[8 * lds]);
        a[2] = __float_as_uint(q[4]);
        a[3] = __float_as_uint(q[8 * lds + 4]);
#pragma unroll
        for (int nb = 0; nb < 4; ++nb) {
            const uint4 B = sWf[(kc * 8 + cg * 4 + nb) * 32 + lane];
            mma8(acc[nb], a, B.x, B.y);   // W_hi
            mma8(acc[nb], a, B.z, B.w);   // W_lo
        }
    }
}

// =====================================================================================
// EDGE PASS: h = relu([x[col] || ea] @ W1a + b1a); red-scatter h; count degrees.
// 320 threads = 5 warp-pairs; tile = 32 rows; warp = 32 rows x 32 cols (X=2,Y=4).
// Double-buffered cp.async gather; B-frags reused across 2 row groups.
// =====================================================================================
#define ENT 320
#define EPAIRS 5
// smem floats: W1 nb-packed frags 8192 (32KB) | ba 64 | pairs at 8256, stride 8704:
//   A0 32x132 (4224) | A1 4224 | ringRow 4x32 int | ringCol 4x32 int
#define E_PPF 8704
#define E_SMEM_F (8256 + EPAIRS * E_PPF)
#define E_SMEM_B (E_SMEM_F * 4)   // 207,104 B

__device__ __forceinline__ void load_idx_e(const void* ei, bool is64, int tbase,
                                           int* rs, int* cs, int pt) {
    if (pt < 32) {
        const int ge = tbase + pt;
        int r, c;
        if (is64) {
            const long long* e64 = reinterpret_cast<const long long*>(ei);
            r = (int)e64[ge]; c = (int)e64[N_EDGES + ge];
        } else {
            const int* e32 = reinterpret_cast<const int*>(ei);
            r = e32[ge]; c = e32[N_EDGES + ge];
        }
        atomicAdd(&g_counts[r], 1.0f);
        rs[pt] = r; cs[pt] = c;
    }
}

__device__ __forceinline__ void gather_cp_e(int base, const int* cols,
                                            const float* __restrict__ x,
                                            const float* __restrict__ ea,
                                            uint32_t a_dst, int pt) {
#pragma unroll
    for (int it = 0; it < 16; ++it) {
        const int i = it * 64 + pt;          // [0, 1024)
        const int row = i >> 5, q = i & 31;  // 32 rows x 32 16B-chunks
        const void* src;
        if (q < 16) src = (const char*)x  + ((size_t)cols[row] * 64 + q * 4) * 4;
        else        src = (const char*)ea + ((size_t)(base + row) * 64 + (q - 16) * 4) * 4;
        cp16(a_dst + (uint32_t)(row * 132 + q * 4) * 4, src);
    }
}

__global__ void __launch_bounds__(ENT, 1)
edge_pass(const float* __restrict__ x, const void* __restrict__ ei,
          const float* __restrict__ ea,
          const float* __restrict__ Wa, const float* __restrict__ ba)
{
    extern __shared__ float sm[];
    uint4* sW  = reinterpret_cast<uint4*>(sm);
    float* sBa = sm + 8192;
    const int tid = threadIdx.x, lane = tid & 31;
    const int tg = lane >> 2, tc = lane & 3;
    const int pr = tid >> 6, pt = tid & 63, cg = (tid >> 5) & 1;

    float* pb = sm + 8256 + pr * E_PPF;
    float* A0 = pb;
    float* A1 = pb + 4224;
    int* ringR = reinterpret_cast<int*>(pb + 8448);   // 4 x 32
    int* ringC = ringR + 128;                          // 4 x 32
    const uint32_t aU[2] = {smem_u32(A0), smem_u32(A1)};
    const float* Ab[2] = {A0, A1};

    stage_w_p4<16, ENT>(sW, Wa, tid);
    if (tid < 64) sBa[tid] = ba[tid];
    __syncthreads();

    // dtype sniff: int64 edge_index has zero high words for small nonneg values
    const int* e32 = reinterpret_cast<const int*>(ei);
    const bool is64 = ((e32[1] | e32[3] | e32[5] | e32[7]) == 0);

    const int NP = gridDim.x * EPAIRS;
    const int gp = blockIdx.x * EPAIRS + pr;
    const int ntiles = N_EDGES / 32;       // exact: 25000

    // prologue: idx tiles 0,1; cp.async tile 0
    if (gp < ntiles) load_idx_e(ei, is64, gp * 32, ringR, ringC, pt);
    if (gp + NP < ntiles)
        load_idx_e(ei, is64, (gp + NP) * 32, ringR + 32, ringC + 32, pt);
    barp(pr + 1);
    if (gp < ntiles) {
        gather_cp_e(gp * 32, ringC, x, ea, aU[0], pt);
        cp_commit();
    }

    for (int j = 0; gp + j * NP < ntiles; ++j) {
        const bool hasN = gp + (j + 1) * NP < ntiles;
        // prefetch next tile; idx two ahead
        if (hasN) {
            gather_cp_e((gp + (j + 1) * NP) * 32, ringC + ((j + 1) & 3) * 32,
                        x, ea, aU[(j + 1) & 1], pt);
            cp_commit();
        }
        if (gp + (j + 2) * NP < ntiles)
            load_idx_e(ei, is64, (gp + (j + 2) * NP) * 32,
                       ringR + ((j + 2) & 3) * 32, ringC + ((j + 2) & 3) * 32, pt);
        if (hasN) cp_wait<1>(); else cp_wait<0>();
        barp(pr + 1);   // cp.async data + idx ring visible pair-wide

        // ---- GEMM1: [32x128] @ [128x64], X=2 row groups, nb-pair packed B ----
        const float* sA = Ab[j & 1];
        float acc[2][4][4];
#pragma unroll
        for (int g = 0; g < 2; ++g)
#pragma unroll
            for (int nb = 0; nb < 4; ++nb)
#pragma unroll
                for (int v = 0; v < 4; ++v) acc[g][nb][v] = 0.0f;
#pragma unroll 4
        for (int kc = 0; kc < 16; ++kc) {
            uint32_t a[2][4];
#pragma unroll
            for (int g = 0; g < 2; ++g) {
                const float* q = sA + (tg + 16 * g) * 132 + kc * 8 + tc;
                a[g][0] = __float_as_uint(q[0]);
                a[g][1] = __float_as_uint(q[8 * 132]);
                a[g][2] = __float_as_uint(q[4]);
                a[g][3] = __float_as_uint(q[8 * 132 + 4]);
            }
#pragma unroll
            for (int p = 0; p < 2; ++p) {
                const uint4 B = sW[(kc * 4 + cg * 2 + p) * 32 + lane];
                mma8(acc[0][2 * p],     a[0], B.x, B.y);
                mma8(acc[0][2 * p + 1], a[0], B.z, B.w);
                mma8(acc[1][2 * p],     a[1], B.x, B.y);
                mma8(acc[1][2 * p + 1], a[1], B.z, B.w);
            }
        }

        // ---- epilogue: relu(+bias) -> shuffle-combine -> red4 from registers ----
        const int* rows = ringR + (j & 3) * 32;
#pragma unroll
        for (int g = 0; g < 2; ++g) {
            const int rnode = (tc & 1) ? rows[tg + 8 + 16 * g] : rows[tg + 16 * g];
            float* dst = g_summed + (size_t)rnode * 64;
#pragma unroll
            for (int nb = 0; nb < 4; ++nb) {
                const int col0 = cg * 32 + nb * 8 + 2 * tc;
                const float2 bi = *reinterpret_cast<const float2*>(sBa + col0);
                const float h0 = fmaxf(acc[g][nb][0] + bi.x, 0.0f);
                const float h1 = fmaxf(acc[g][nb][1] + bi.y, 0.0f);
                const float h2 = fmaxf(acc[g][nb][2] + bi.x, 0.0f);
                const float h3 = fmaxf(acc[g][nb][3] + bi.y, 0.0f);
                const float p0 = __shfl_xor_sync(0xffffffffu, h0, 1);
                const float p1 = __shfl_xor_sync(0xffffffffu, h1, 1);
                const float p2 = __shfl_xor_sync(0xffffffffu, h2, 1);
                const float p3 = __shfl_xor_sync(0xffffffffu, h3, 1);
                if (tc & 1)   // row tg+8+16g, cols col0-2 .. col0+1
                    red4(dst + (col0 - 2), make_float4(p2, p3, h2, h3));
                else          // row tg+16g, cols col0 .. col0+3
                    red4(dst + col0, make_float4(h0, h1, p0, p1));
            }
        }
        barp(pr + 1);   // both warps past GEMM1 reads -> next cp.async target safe
    }
}

// =====================================================================================
// AGG PASS: g_agg[n] = (g_summed[n]/max(cnt,1)) @ W1b + (cnt>0 ? b1b : 0)
// Exact hi/lo weights.
// =====================================================================================
#define ANT 512
#define APAIRS 8
// smem floats: W1b hilo frags 8192 (32KB) | bb 64 | pairs at 8256, stride 1104
#define A_SMEM_F (8256 + APAIRS * 1104)
#define A_SMEM_B (A_SMEM_F * 4)

__global__ void __launch_bounds__(ANT, 1)
agg_pass(const float* __restrict__ Wb, const float* __restrict__ bb)
{
    extern __shared__ float sm[];
    uint4* sW  = reinterpret_cast<uint4*>(sm);
    float* sBb = sm + 8192;
    const int tid = threadIdx.x, lane = tid & 31;
    const int tg = lane >> 2, tc = lane & 3;
    const int pr = tid >> 6, pt = tid & 63, cg = (tid >> 5) & 1;

    float* sA   = sm + 8256 + pr * 1104;
    float* sCnt = sA + 1088;

    stage_w_hl<8, ANT>(sW, Wb, tid);
    if (tid < 64) sBb[tid] = bb[tid];
    __syncthreads();

    const int NP = gridDim.x * APAIRS;
    const int gp = blockIdx.x * APAIRS + pr;
    const int ntiles = N_NODES / 16;   // exact

    for (int j = 0; gp + j * NP < ntiles; ++j) {
        const int base = (gp + j * NP) * 16;
#pragma unroll
        for (int it = 0; it < 4; ++it) {
            const int i = it * 64 + pt;          // [0, 256)
            const int row = i >> 4, q = i & 15;
            const int n = base + row;
            const float cnt = g_counts[n];
            const float s = 1.0f / fmaxf(cnt, 1.0f);
            float4 v = reinterpret_cast<const float4*>(g_summed)[(size_t)n * 16 + q];
            v.x *= s; v.y *= s; v.z *= s; v.w *= s;
            *reinterpret_cast<float4*>(sA + row * 68 + q * 4) = v;
            sCnt[row] = cnt;
        }
        barp(pr + 1);

        float acc[4][4];
        gemm_hl<8>(sA, 68, sW, tg, tc, lane, cg, acc);

        const float ca = sCnt[tg], cb = sCnt[tg + 8];
#pragma unroll
        for (int nb = 0; nb < 4; ++nb) {
            const int col0 = cg * 32 + nb * 8 + 2 * tc;
            const float2 bi = *reinterpret_cast<const float2*>(sBb + col0);
            float2 oa = make_float2(acc[nb][0] + (ca > 0.0f ? bi.x : 0.0f),
                                    acc[nb][1] + (ca > 0.0f ? bi.y : 0.0f));
            float2 ob = make_float2(acc[nb][2] + (cb > 0.0f ? bi.x : 0.0f),
                                    acc[nb][3] + (cb > 0.0f ? bi.y : 0.0f));
            *reinterpret_cast<float2*>(g_agg + (size_t)(base + tg) * 64 + col0)     = oa;
            *reinterpret_cast<float2*>(g_agg + (size_t)(base + tg + 8) * 64 + col0) = ob;
        }
        barp(pr + 1);   // sA/sCnt reuse safe
    }
}

// =====================================================================================
// NODE PASS: out = relu([x || g_agg] @ W2a + b2a) @ W2b + b2b
// Exact hi/lo weights for both GEMMs.
// =====================================================================================
#define NNT 640
#define NPAIRS 10
// smem floats: W2a hilo 16384 (64KB) | W2b hilo 8192 (32KB) | ba 64 | bb 64 |
//   pairs at 24704, stride 3200: A 16x132 (2112) + H 16x68 (1088)
#define N_SMEM_F (24704 + NPAIRS * 3200)
#define N_SMEM_B (N_SMEM_F * 4)   // 226,816 B

__global__ void __launch_bounds__(NNT, 1)
node_pass(const float* __restrict__ x,
          const float* __restrict__ Wa, const float* __restrict__ ba,
          const float* __restrict__ Wb, const float* __restrict__ bb,
          float* __restrict__ outp)
{
    extern __shared__ float sm[];
    uint4* sWa = reinterpret_cast<uint4*>(sm);
    uint4* sWb = reinterpret_cast<uint4*>(sm + 16384);
    float* sBa = sm + 24576;
    float* sBb = sm + 24640;
    const int tid = threadIdx.x, lane = tid & 31;
    const int tg = lane >> 2, tc = lane & 3;
    const int pr = tid >> 6, pt = tid & 63, cg = (tid >> 5) & 1;

    float* sA = sm + 24704 + pr * 3200;
    float* sH = sA + 2112;

    stage_w_hl<16, NNT>(sWa, Wa, tid);
    stage_w_hl<8, NNT>(sWb, Wb, tid);
    if (tid < 64) { sBa[tid] = ba[tid]; sBb[tid] = bb[tid]; }
    __syncthreads();

    const int NP = gridDim.x * NPAIRS;
    const int gp = blockIdx.x * NPAIRS + pr;
    const int ntiles = N_NODES / 16;   // exact

    for (int j = 0; gp + j * NP < ntiles; ++j) {
        const int base = (gp + j * NP) * 16;
#pragma unroll
        for (int it = 0; it < 8; ++it) {
            const int i = it * 64 + pt;
            const int row = i >> 5, q = i & 31;
            const int n = base + row;
            float4 v;
            if (q < 16) v = reinterpret_cast<const float4*>(x)[(size_t)n * 16 + q];
            else        v = reinterpret_cast<const float4*>(g_agg)[(size_t)n * 16 + (q - 16)];
            *reinterpret_cast<float4*>(sA + row * 132 + q * 4) = v;
        }
        barp(pr + 1);

        float acc[4][4];
        gemm_hl<16>(sA, 132, sWa, tg, tc, lane, cg, acc);

        // relu + b2a -> H (stride 68)
#pragma unroll
        for (int nb = 0; nb < 4; ++nb) {
            const int col0 = cg * 32 + nb * 8 + 2 * tc;
            const float2 bi = *reinterpret_cast<const float2*>(sBa + col0);
            *reinterpret_cast<float2*>(sH + tg * 68 + col0) =
                make_float2(fmaxf(acc[nb][0] + bi.x, 0.0f), fmaxf(acc[nb][1] + bi.y, 0.0f));
            *reinterpret_cast<float2*>(sH + (tg + 8) * 68 + col0) =
                make_float2(fmaxf(acc[nb][2] + bi.x, 0.0f), fmaxf(acc[nb][3] + bi.y, 0.0f));
        }
        barp(pr + 1);

        float acc2[4][4];
        gemm_hl<8>(sH, 68, sWb, tg, tc, lane, cg, acc2);

#pragma unroll
        for (int nb = 0; nb < 4; ++nb) {
            const int col0 = cg * 32 + nb * 8 + 2 * tc;
            const float2 bi = *reinterpret_cast<const float2*>(sBb + col0);
            *reinterpret_cast<float2*>(outp + (size_t)(base + tg) * 64 + col0) =
                make_float2(acc2[nb][0] + bi.x, acc2[nb][1] + bi.y);
            *reinterpret_cast<float2*>(outp + (size_t)(base + tg + 8) * 64 + col0) =
                make_float2(acc2[nb][2] + bi.x, acc2[nb][3] + bi.y);
        }
        barp(pr + 1);   // sA/sH reuse safe
    }
}

// ---------------- launch ----------------------------------------------------------------
extern "C" void kernel_launch(void* const* d_in, const int* in_sizes, int n_in,
                              void* d_out, int out_size) {
    const float* x   = reinterpret_cast<const float*>(d_in[0]);
    const void*  ei  = d_in[1];
    const float* ea  = reinterpret_cast<const float*>(d_in[2]);
    const float* W1a = reinterpret_cast<const float*>(d_in[5]);
    const float* b1a = reinterpret_cast<const float*>(d_in[6]);
    const float* W1b = reinterpret_cast<const float*>(d_in[7]);
    const float* b1b = reinterpret_cast<const float*>(d_in[8]);
    const float* W2a = reinterpret_cast<const float*>(d_in[9]);
    const float* b2a = reinterpret_cast<const float*>(d_in[10]);
    const float* W2b = reinterpret_cast<const float*>(d_in[11]);
    const float* b2b = reinterpret_cast<const float*>(d_in[12]);
    float* out = reinterpret_cast<float*>(d_out);

    cudaFuncSetAttribute(edge_pass, cudaFuncAttributeMaxDynamicSharedMemorySize, E_SMEM_B);
    cudaFuncSetAttribute(agg_pass,  cudaFuncAttributeMaxDynamicSharedMemorySize, A_SMEM_B);
    cudaFuncSetAttribute(node_pass, cudaFuncAttributeMaxDynamicSharedMemorySize, N_SMEM_B);

    void* gs = nullptr; void* gc = nullptr;
    cudaGetSymbolAddress(&gs, g_summed);
    cudaGetSymbolAddress(&gc, g_counts);
    cudaMemsetAsync(gs, 0, (size_t)N_NODES * 64 * sizeof(float));
    cudaMemsetAsync(gc, 0, (size_t)N_NODES * sizeof(float));

    edge_pass<<<148, ENT, E_SMEM_B>>>(x, ei, ea, W1a, b1a);
    agg_pass<<<148, ANT, A_SMEM_B>>>(W1b, b1b);
    node_pass<<<148, NNT, N_SMEM_B>>>(x, W2a, b2a, W2b, b2b, out);
}

// round 8
// speedup vs baseline: 1.2799x; 1.2799x over previous
#include <cuda_runtime.h>
#include <cstdint>

#define N_NODES 50000
#define N_EDGES 800000

// ---------------- scratch (static device allocation) ---------------------------
__device__ float g_summed[N_NODES * 64];   // scatter-sum of hidden h (pre-W1b)
__device__ float g_counts[N_NODES];
__device__ float g_agg[N_NODES * 64];      // (summed/cnt)@W1b + b1b

// ---------------- helpers -------------------------------------------------------
__device__ __forceinline__ uint32_t smem_u32(const void* p) {
    uint32_t a;
    asm("{ .reg .u64 t; cvta.to.shared.u64 t, %1; cvt.u32.u64 %0, t; }" : "=r"(a) : "l"(p));
    return a;
}
__device__ __forceinline__ uint32_t to_tf32(float f) {
    uint32_t r; asm("cvt.rna.tf32.f32 %0, %1;" : "=r"(r) : "f"(f)); return r;
}
__device__ __forceinline__ void red4(float* a, float4 v) {
    asm volatile("red.global.add.v4.f32 [%0], {%1,%2,%3,%4};"
                 :: "l"(a), "f"(v.x), "f"(v.y), "f"(v.z), "f"(v.w) : "memory");
}
__device__ __forceinline__ void barp(int id) {
    asm volatile("bar.sync %0, 64;" :: "r"(id) : "memory");
}
__device__ __forceinline__ void cp16(uint32_t dst, const void* src) {
    asm volatile("cp.async.cg.shared.global [%0], [%1], 16;" :: "r"(dst), "l"(src) : "memory");
}
__device__ __forceinline__ void cp_commit() {
    asm volatile("cp.async.commit_group;" ::: "memory");
}
template <int N> __device__ __forceinline__ void cp_wait() {
    asm volatile("cp.async.wait_group %0;" :: "n"(N) : "memory");
}
// m16n8k8 tf32 MMA. g = lane>>2, c = lane&3:
//   A: a0=A[g][c] a1=A[g+8][c] a2=A[g][c+4] a3=A[g+8][c+4]
//   B: b0=B[c][n] b1=B[c+4][n]  (n = lane>>2)
//   D: d0=D[g][2c] d1=D[g][2c+1] d2=D[g+8][2c] d3=D[g+8][2c+1]
__device__ __forceinline__ void mma8(float d[4], const uint32_t a[4],
                                     uint32_t b0, uint32_t b1) {
    asm("mma.sync.aligned.m16n8k8.row.col.f32.tf32.tf32.f32 "
        "{%0,%1,%2,%3}, {%4,%5,%6,%7}, {%8,%9}, {%0,%1,%2,%3};"
        : "+f"(d[0]), "+f"(d[1]), "+f"(d[2]), "+f"(d[3])
        : "r"(a[0]), "r"(a[1]), "r"(a[2]), "r"(a[3]), "r"(b0), "r"(b1));
}

// ---------------- weight staging --------------------------------------------------
// (a) nb-pair packed, single tf32 (edge): sW[(kc*4+nbp)*32+lane] =
//     {b0(nb=2nbp), b1(nb=2nbp), b0(nb=2nbp+1), b1(nb=2nbp+1)}
template <int KC, int NTHR>
__device__ __forceinline__ void stage_w_p4(uint4* sW, const float* __restrict__ W, int tid) {
    for (int i = tid; i < KC * 128; i += NTHR) {
        const int kc = i >> 7, nbp = (i >> 5) & 3, t = i & 31;
        const int k0 = kc * 8 + (t & 3);
        const int n0 = (2 * nbp) * 8 + (t >> 2), n1 = n0 + 8;
        uint4 fr;
        fr.x = to_tf32(W[k0 * 64 + n0]);
        fr.y = to_tf32(W[(k0 + 4) * 64 + n0]);
        fr.z = to_tf32(W[k0 * 64 + n1]);
        fr.w = to_tf32(W[(k0 + 4) * 64 + n1]);
        sW[i] = fr;
    }
}
// (b) plain single tf32 (agg/node): sW[(kc*8+nb)*32 + lane] = {b0, b1}
template <int KC, int NTHR>
__device__ __forceinline__ void stage_w(uint2* sW, const float* __restrict__ W, int tid) {
    for (int i = tid; i < KC * 256; i += NTHR) {
        const int kc = i >> 8, nb = (i >> 5) & 7, t = i & 31;
        const int k0 = kc * 8 + (t & 3), n = nb * 8 + (t >> 2);
        uint2 fr;
        fr.x = to_tf32(W[k0 * 64 + n]);
        fr.y = to_tf32(W[(k0 + 4) * 64 + n]);
        sW[i] = fr;
    }
}

// ---------------- GEMM core (agg/node): warp = 16 rows x 32 cols --------------------
template <int KC>
__device__ __forceinline__ void gemm(const float* __restrict__ sIn, int lds,
                                     const uint2* __restrict__ sWf,
                                     int tg, int tc, int lane, int cg, float acc[4][4]) {
#pragma unroll
    for (int nb = 0; nb < 4; ++nb)
#pragma unroll
        for (int j = 0; j < 4; ++j) acc[nb][j] = 0.0f;
    const float* p0 = sIn + tg * lds;
#pragma unroll 4
    for (int kc = 0; kc < KC; ++kc) {
        const float* q = p0 + kc * 8 + tc;
        uint32_t a[4];
        a[0] = __float_as_uint(q[0]);
        a[1] = __float_as_uint(q[8 * lds]);
        a[2] = __float_as_uint(q[4]);
        a[3] = __float_as_uint(q[8 * lds + 4]);
#pragma unroll
        for (int nb = 0; nb < 4; ++nb) {
            const uint2 B = sWf[(kc * 8 + cg * 4 + nb) * 32 + lane];
            mma8(acc[nb], a, B.x, B.y);
        }
    }
}

// =====================================================================================
// EDGE PASS: h = relu([x[col] || ea] @ W1a + b1a); red-scatter h; count degrees.
// 640 threads = 10 warp-pairs; tile = 32 rows; warp = 32 rows (X=2) x 32 cols.
// SINGLE A buffer per pair; next tile's cp.async overlaps scatter epilogue.
// =====================================================================================
#define ENT 640
#define EPAIRS 10
// smem floats: W1 nb-packed frags 8192 (32KB) | ba 64 | pairs at 8256, stride 4480:
//   A 32x132 (4224) | ringRow 4x32 int | ringCol 4x32 int
#define E_PPF 4480
#define E_SMEM_F (8256 + EPAIRS * E_PPF)
#define E_SMEM_B (E_SMEM_F * 4)   // 212,224 B

__device__ __forceinline__ void load_idx_e(const void* ei, bool is64, int tbase,
                                           int* rs, int* cs, int pt) {
    if (pt < 32) {
        const int ge = tbase + pt;
        int r, c;
        if (is64) {
            const long long* e64 = reinterpret_cast<const long long*>(ei);
            r = (int)e64[ge]; c = (int)e64[N_EDGES + ge];
        } else {
            const int* e32 = reinterpret_cast<const int*>(ei);
            r = e32[ge]; c = e32[N_EDGES + ge];
        }
        atomicAdd(&g_counts[r], 1.0f);
        rs[pt] = r; cs[pt] = c;
    }
}

__device__ __forceinline__ void gather_cp_e(int base, const int* cols,
                                            const float* __restrict__ x,
                                            const float* __restrict__ ea,
                                            uint32_t a_dst, int pt) {
#pragma unroll
    for (int it = 0; it < 16; ++it) {
        const int i = it * 64 + pt;          // [0, 1024)
        const int row = i >> 5, q = i & 31;  // 32 rows x 32 16B-chunks
        const void* src;
        if (q < 16) src = (const char*)x  + ((size_t)cols[row] * 64 + q * 4) * 4;
        else        src = (const char*)ea + ((size_t)(base + row) * 64 + (q - 16) * 4) * 4;
        cp16(a_dst + (uint32_t)(row * 132 + q * 4) * 4, src);
    }
}

__global__ void __launch_bounds__(ENT, 1)
edge_pass(const float* __restrict__ x, const void* __restrict__ ei,
          const float* __restrict__ ea,
          const float* __restrict__ Wa, const float* __restrict__ ba)
{
    extern __shared__ float sm[];
    uint4* sW  = reinterpret_cast<uint4*>(sm);
    float* sBa = sm + 8192;
    const int tid = threadIdx.x, lane = tid & 31;
    const int tg = lane >> 2, tc = lane & 3;
    const int pr = tid >> 6, pt = tid & 63, cg = (tid >> 5) & 1;

    float* sA = sm + 8256 + pr * E_PPF;            // 32x132 single buffer
    int* ringR = reinterpret_cast<int*>(sA + 4224); // 4 x 32
    int* ringC = ringR + 128;                       // 4 x 32
    const uint32_t aU = smem_u32(sA);

    stage_w_p4<16, ENT>(sW, Wa, tid);
    if (tid < 64) sBa[tid] = ba[tid];
    __syncthreads();

    // dtype sniff: int64 edge_index has zero high words for small nonneg values
    const int* e32s = reinterpret_cast<const int*>(ei);
    const bool is64 = ((e32s[1] | e32s[3] | e32s[5] | e32s[7]) == 0);

    const int NP = gridDim.x * EPAIRS;
    const int gp = blockIdx.x * EPAIRS + pr;
    const int ntiles = N_EDGES / 32;       // exact: 25000

    // prologue: idx tiles 0,1; cp.async tile 0 into A
    if (gp < ntiles) load_idx_e(ei, is64, gp * 32, ringR, ringC, pt);
    if (gp + NP < ntiles)
        load_idx_e(ei, is64, (gp + NP) * 32, ringR + 32, ringC + 32, pt);
    barp(pr + 1);
    if (gp < ntiles) {
        gather_cp_e(gp * 32, ringC, x, ea, aU, pt);
        cp_commit();
    }

    for (int j = 0; gp + j * NP < ntiles; ++j) {
        const bool hasN = gp + (j + 1) * NP < ntiles;

        cp_wait<0>();
        barp(pr + 1);   // tile j data visible pair-wide

        // ---- GEMM1: [32x128] @ [128x64], X=2 row groups, nb-pair packed B ----
        float acc[2][4][4];
#pragma unroll
        for (int g = 0; g < 2; ++g)
#pragma unroll
            for (int nb = 0; nb < 4; ++nb)
#pragma unroll
                for (int v = 0; v < 4; ++v) acc[g][nb][v] = 0.0f;
#pragma unroll 4
        for (int kc = 0; kc < 16; ++kc) {
            uint32_t a[2][4];
#pragma unroll
            for (int g = 0; g < 2; ++g) {
                const float* q = sA + (tg + 16 * g) * 132 + kc * 8 + tc;
                a[g][0] = __float_as_uint(q[0]);
                a[g][1] = __float_as_uint(q[8 * 132]);
                a[g][2] = __float_as_uint(q[4]);
                a[g][3] = __float_as_uint(q[8 * 132 + 4]);
            }
#pragma unroll
            for (int p = 0; p < 2; ++p) {
                const uint4 B = sW[(kc * 4 + cg * 2 + p) * 32 + lane];
                mma8(acc[0][2 * p],     a[0], B.x, B.y);
                mma8(acc[0][2 * p + 1], a[0], B.z, B.w);
                mma8(acc[1][2 * p],     a[1], B.x, B.y);
                mma8(acc[1][2 * p + 1], a[1], B.z, B.w);
            }
        }
        barp(pr + 1);   // both warps done reading A -> refill is safe

        // ---- issue next tile's cp.async NOW (overlaps scatter epilogue) ----
        if (hasN) {
            gather_cp_e((gp + (j + 1) * NP) * 32, ringC + ((j + 1) & 3) * 32,
                        x, ea, aU, pt);
            cp_commit();
        }
        // idx two ahead (ring slot (j+2)&3 last used by tile j-2: free)
        if (gp + (j + 2) * NP < ntiles)
            load_idx_e(ei, is64, (gp + (j + 2) * NP) * 32,
                       ringR + ((j + 2) & 3) * 32, ringC + ((j + 2) & 3) * 32, pt);

        // ---- epilogue: relu(+bias) -> shuffle-combine -> red4 from registers ----
        const int* rows = ringR + (j & 3) * 32;
#pragma unroll
        for (int g = 0; g < 2; ++g) {
            const int rnode = (tc & 1) ? rows[tg + 8 + 16 * g] : rows[tg + 16 * g];
            float* dst = g_summed + (size_t)rnode * 64;
#pragma unroll
            for (int nb = 0; nb < 4; ++nb) {
                const int col0 = cg * 32 + nb * 8 + 2 * tc;
                const float2 bi = *reinterpret_cast<const float2*>(sBa + col0);
                const float h0 = fmaxf(acc[g][nb][0] + bi.x, 0.0f);
                const float h1 = fmaxf(acc[g][nb][1] + bi.y, 0.0f);
                const float h2 = fmaxf(acc[g][nb][2] + bi.x, 0.0f);
                const float h3 = fmaxf(acc[g][nb][3] + bi.y, 0.0f);
                const float p0 = __shfl_xor_sync(0xffffffffu, h0, 1);
                const float p1 = __shfl_xor_sync(0xffffffffu, h1, 1);
                const float p2 = __shfl_xor_sync(0xffffffffu, h2, 1);
                const float p3 = __shfl_xor_sync(0xffffffffu, h3, 1);
                if (tc & 1)   // row tg+8+16g, cols col0-2 .. col0+1
                    red4(dst + (col0 - 2), make_float4(p2, p3, h2, h3));
                else          // row tg+16g, cols col0 .. col0+3
                    red4(dst + col0, make_float4(h0, h1, p0, p1));
            }
        }
    }
}

// =====================================================================================
// AGG PASS: g_agg[n] = (g_summed[n]/max(cnt,1)) @ W1b + (cnt>0 ? b1b : 0)
// =====================================================================================
#define ANT 512
#define APAIRS 8
// smem floats: W1b frags 4096 | bb 64 | pairs at 4160, stride 1104: A 16x68 + cnt 16
#define A_SMEM_F (4160 + APAIRS * 1104)
#define A_SMEM_B (A_SMEM_F * 4)

__global__ void __launch_bounds__(ANT, 1)
agg_pass(const float* __restrict__ Wb, const float* __restrict__ bb)
{
    extern __shared__ float sm[];
    uint2* sW  = reinterpret_cast<uint2*>(sm);
    float* sBb = sm + 4096;
    const int tid = threadIdx.x, lane = tid & 31;
    const int tg = lane >> 2, tc = lane & 3;
    const int pr = tid >> 6, pt = tid & 63, cg = (tid >> 5) & 1;

    float* sA   = sm + 4160 + pr * 1104;
    float* sCnt = sA + 1088;

    stage_w<8, ANT>(sW, Wb, tid);
    if (tid < 64) sBb[tid] = bb[tid];
    __syncthreads();

    const int NP = gridDim.x * APAIRS;
    const int gp = blockIdx.x * APAIRS + pr;
    const int ntiles = N_NODES / 16;   // exact

    for (int j = 0; gp + j * NP < ntiles; ++j) {
        const int base = (gp + j * NP) * 16;
#pragma unroll
        for (int it = 0; it < 4; ++it) {
            const int i = it * 64 + pt;          // [0, 256)
            const int row = i >> 4, q = i & 15;
            const int n = base + row;
            const float cnt = g_counts[n];
            const float s = 1.0f / fmaxf(cnt, 1.0f);
            float4 v = reinterpret_cast<const float4*>(g_summed)[(size_t)n * 16 + q];
            v.x *= s; v.y *= s; v.z *= s; v.w *= s;
            *reinterpret_cast<float4*>(sA + row * 68 + q * 4) = v;
            sCnt[row] = cnt;
        }
        barp(pr + 1);

        float acc[4][4];
        gemm<8>(sA, 68, sW, tg, tc, lane, cg, acc);

        const float ca = sCnt[tg], cb = sCnt[tg + 8];
#pragma unroll
        for (int nb = 0; nb < 4; ++nb) {
            const int col0 = cg * 32 + nb * 8 + 2 * tc;
            const float2 bi = *reinterpret_cast<const float2*>(sBb + col0);
            float2 oa = make_float2(acc[nb][0] + (ca > 0.0f ? bi.x : 0.0f),
                                    acc[nb][1] + (ca > 0.0f ? bi.y : 0.0f));
            float2 ob = make_float2(acc[nb][2] + (cb > 0.0f ? bi.x : 0.0f),
                                    acc[nb][3] + (cb > 0.0f ? bi.y : 0.0f));
            *reinterpret_cast<float2*>(g_agg + (size_t)(base + tg) * 64 + col0)     = oa;
            *reinterpret_cast<float2*>(g_agg + (size_t)(base + tg + 8) * 64 + col0) = ob;
        }
        barp(pr + 1);   // sA/sCnt reuse safe
    }
}

// =====================================================================================
// NODE PASS: out = relu([x || g_agg] @ W2a + b2a) @ W2b + b2b
// =====================================================================================
#define NNT 704
#define NPAIRS 11
// smem floats: W2a frags 8192 | W2b frags 4096 | ba 64 | bb 64 | pairs at 12416,
//   stride 3200: A 16x132 (2112) + H 16x68 (1088)
#define N_SMEM_F (12416 + NPAIRS * 3200)
#define N_SMEM_B (N_SMEM_F * 4)

__global__ void __launch_bounds__(NNT, 1)
node_pass(const float* __restrict__ x,
          const float* __restrict__ Wa, const float* __restrict__ ba,
          const float* __restrict__ Wb, const float* __restrict__ bb,
          float* __restrict__ outp)
{
    extern __shared__ float sm[];
    uint2* sWa = reinterpret_cast<uint2*>(sm);
    uint2* sWb = reinterpret_cast<uint2*>(sm + 8192);
    float* sBa = sm + 12288;
    float* sBb = sm + 12352;
    const int tid = threadIdx.x, lane = tid & 31;
    const int tg = lane >> 2, tc = lane & 3;
    const int pr = tid >> 6, pt = tid & 63, cg = (tid >> 5) & 1;

    float* sA = sm + 12416 + pr * 3200;
    float* sH = sA + 2112;

    stage_w<16, NNT>(sWa, Wa, tid);
    stage_w<8, NNT>(sWb, Wb, tid);
    if (tid < 64) { sBa[tid] = ba[tid]; sBb[tid] = bb[tid]; }
    __syncthreads();

    const int NP = gridDim.x * NPAIRS;
    const int gp = blockIdx.x * NPAIRS + pr;
    const int ntiles = N_NODES / 16;   // exact

    for (int j = 0; gp + j * NP < ntiles; ++j) {
        const int base = (gp + j * NP) * 16;
#pragma unroll
        for (int it = 0; it < 8; ++it) {
            const int i = it * 64 + pt;
            const int row = i >> 5, q = i & 31;
            const int n = base + row;
            float4 v;
            if (q < 16) v = reinterpret_cast<const float4*>(x)[(size_t)n * 16 + q];
            else        v = reinterpret_cast<const float4*>(g_agg)[(size_t)n * 16 + (q - 16)];
            *reinterpret_cast<float4*>(sA + row * 132 + q * 4) = v;
        }
        barp(pr + 1);

        float acc[4][4];
        gemm<16>(sA, 132, sWa, tg, tc, lane, cg, acc);

        // relu + b2a -> H (stride 68)
#pragma unroll
        for (int nb = 0; nb < 4; ++nb) {
            const int col0 = cg * 32 + nb * 8 + 2 * tc;
            const float2 bi = *reinterpret_cast<const float2*>(sBa + col0);
            *reinterpret_cast<float2*>(sH + tg * 68 + col0) =
                make_float2(fmaxf(acc[nb][0] + bi.x, 0.0f), fmaxf(acc[nb][1] + bi.y, 0.0f));
            *reinterpret_cast<float2*>(sH + (tg + 8) * 68 + col0) =
                make_float2(fmaxf(acc[nb][2] + bi.x, 0.0f), fmaxf(acc[nb][3] + bi.y, 0.0f));
        }
        barp(pr + 1);

        float acc2[4][4];
        gemm<8>(sH, 68, sWb, tg, tc, lane, cg, acc2);

#pragma unroll
        for (int nb = 0; nb < 4; ++nb) {
            const int col0 = cg * 32 + nb * 8 + 2 * tc;
            const float2 bi = *reinterpret_cast<const float2*>(sBb + col0);
            *reinterpret_cast<float2*>(outp + (size_t)(base + tg) * 64 + col0) =
                make_float2(acc2[nb][0] + bi.x, acc2[nb][1] + bi.y);
            *reinterpret_cast<float2*>(outp + (size_t)(base + tg + 8) * 64 + col0) =
                make_float2(acc2[nb][2] + bi.x, acc2[nb][3] + bi.y);
        }
        barp(pr + 1);   // sA/sH reuse safe
    }
}

// ---------------- launch ----------------------------------------------------------------
extern "C" void kernel_launch(void* const* d_in, const int* in_sizes, int n_in,
                              void* d_out, int out_size) {
    const float* x   = reinterpret_cast<const float*>(d_in[0]);
    const void*  ei  = d_in[1];
    const float* ea  = reinterpret_cast<const float*>(d_in[2]);
    const float* W1a = reinterpret_cast<const float*>(d_in[5]);
    const float* b1a = reinterpret_cast<const float*>(d_in[6]);
    const float* W1b = reinterpret_cast<const float*>(d_in[7]);
    const float* b1b = reinterpret_cast<const float*>(d_in[8]);
    const float* W2a = reinterpret_cast<const float*>(d_in[9]);
    const float* b2a = reinterpret_cast<const float*>(d_in[10]);
    const float* W2b = reinterpret_cast<const float*>(d_in[11]);
    const float* b2b = reinterpret_cast<const float*>(d_in[12]);
    float* out = reinterpret_cast<float*>(d_out);

    cudaFuncSetAttribute(edge_pass, cudaFuncAttributeMaxDynamicSharedMemorySize, E_SMEM_B);
    cudaFuncSetAttribute(agg_pass,  cudaFuncAttributeMaxDynamicSharedMemorySize, A_SMEM_B);
    cudaFuncSetAttribute(node_pass, cudaFuncAttributeMaxDynamicSharedMemorySize, N_SMEM_B);

    void* gs = nullptr; void* gc = nullptr;
    cudaGetSymbolAddress(&gs, g_summed);
    cudaGetSymbolAddress(&gc, g_counts);
    cudaMemsetAsync(gs, 0, (size_t)N_NODES * 64 * sizeof(float));
    cudaMemsetAsync(gc, 0, (size_t)N_NODES * sizeof(float));

    edge_pass<<<148, ENT, E_SMEM_B>>>(x, ei, ea, W1a, b1a);
    agg_pass<<<148, ANT, A_SMEM_B>>>(W1b, b1b);
    node_pass<<<148, NNT, N_SMEM_B>>>(x, W2a, b2a, W2b, b2b, out);
}